// round 17
// baseline (speedup 1.0000x reference)
#include <cuda_runtime.h>
#include <cuda_fp16.h>

#define NN  100000
#define NE  3200000
#define CIN 128
#define HID 16
#define MAXDEG 128   // binomial(3.2M,1e-5): mean 32, max ~57 over 100K nodes

// Scratch (no allocations allowed).
__device__ int   g_degi[NN];             // in-degree (excl. self)
__device__ float g_dinv[NN];             // rsqrt(1+deg)
__device__ int   g_nbr2[NN * MAXDEG];    // fixed-stride CSR (padded to mult-of-4 with NN)
__device__ __align__(16) float g_feat [(NN + 1) * HID];  // layer-1 feats; row NN = zeros
__device__ __align__(16) float g_feat2[(NN + 1) * HID];  // layer-2 feats; row NN = zeros
__device__ uint4 g_h2[NN * 2];           // final embeddings (fp16 rows, 32B)
__device__ int   g_is64;                 // 1 if edge_index is int64, 0 if int32

__device__ __forceinline__ void padd_f32x2(unsigned long long& acc, unsigned long long v) {
    asm("add.rn.f32x2 %0, %0, %1;" : "+l"(acc) : "l"(v));
}

__device__ __forceinline__ int clampi(long long v) {
    v = v < 0 ? 0 : (v >= NN ? NN - 1 : v);
    return (int)v;
}

__device__ __forceinline__ int4 load_idx4(const void* ei, long long pos, int is64) {
    if (!is64) {
        int4 t = __ldg((const int4*)((const int*)ei + pos));
        return make_int4(clampi(t.x), clampi(t.y), clampi(t.z), clampi(t.w));
    } else {
        longlong2 a = __ldg((const longlong2*)((const long long*)ei + pos));
        longlong2 b = __ldg((const longlong2*)((const long long*)ei + pos + 2));
        return make_int4(clampi(a.x), clampi(a.y), clampi(b.x), clampi(b.y));
    }
}

__device__ __forceinline__ int load_idx1(const void* ei, long long pos, int is64) {
    long long v = is64 ? __ldg((const long long*)ei + pos)
                       : (long long)__ldg((const int*)ei + pos);
    return clampi(v);
}

// #1: zero counters + dtype detection (block 0) + zero dummy rows (block 1).
__global__ void k_init(const void* ei) {
    if (blockIdx.x == 0) {
        __shared__ int bad;
        if (threadIdx.x == 0) bad = 0;
        __syncthreads();
        long long pos = (long long)threadIdx.x * (NE / 256);
        long long v = ((const long long*)ei)[pos];
        if (v < 0 || v >= NN) atomicOr(&bad, 1);
        __syncthreads();
        if (threadIdx.x == 0) g_is64 = bad ? 0 : 1;
    }
    if (blockIdx.x == 1 && threadIdx.x < HID) {
        g_feat [NN * HID + threadIdx.x] = 0.f;   // dummy row for padded slots
        g_feat2[NN * HID + threadIdx.x] = 0.f;
    }
    int i = blockIdx.x * blockDim.x + threadIdx.x;
    if (i < NN) g_degi[i] = 0;
}

// #2: count degrees AND scatter source ids into fixed-stride segments.
__global__ void k_deg_store(const void* __restrict__ ei) {
    int t = blockIdx.x * blockDim.x + threadIdx.x;
    long long e = (long long)t * 4;
    if (e >= NE) return;
    int is64 = g_is64;
    int4 r4 = load_idx4(ei, e, is64);
    int4 c4 = load_idx4(ei, (long long)NE + e, is64);
    int rr[4] = {r4.x, r4.y, r4.z, r4.w};
    int cc[4] = {c4.x, c4.y, c4.z, c4.w};
    #pragma unroll
    for (int k = 0; k < 4; k++) {
        int rk = atomicAdd(&g_degi[cc[k]], 1);
        if (rk < MAXDEG) g_nbr2[cc[k] * MAXDEG + rk] = rr[k];
    }
}

// #3: layer-1 transform (16 nodes/block) + dinv + segment padding to mult-of-4.
#define XS_STR 132
__global__ void k_xform1(const float* __restrict__ x, const float* __restrict__ W1) {
    __shared__ float sX[16 * XS_STR];
    __shared__ float sWt[HID * XS_STR];
    const float* xb = x + (size_t)blockIdx.x * 16 * CIN;
    #pragma unroll
    for (int L = threadIdx.x; L < 16 * CIN; L += 256) {
        int n = L >> 7, k = L & 127;
        sX[n * XS_STR + k] = xb[L];
    }
    #pragma unroll
    for (int L = threadIdx.x; L < CIN * HID; L += 256) {
        int k = L >> 4, j = L & 15;
        sWt[j * XS_STR + k] = W1[L];
    }
    __syncthreads();
    int nloc = threadIdx.x >> 4;
    int j    = threadIdx.x & 15;
    int node = blockIdx.x * 16 + nloc;
    const float4* xr = (const float4*)(sX  + nloc * XS_STR);
    const float4* wr = (const float4*)(sWt + j    * XS_STR);
    float acc = 0.f;
    #pragma unroll
    for (int k4 = 0; k4 < CIN / 4; k4++) {
        float4 xv = xr[k4];
        float4 wv = wr[k4];
        acc = fmaf(xv.x, wv.x, acc);
        acc = fmaf(xv.y, wv.y, acc);
        acc = fmaf(xv.z, wv.z, acc);
        acc = fmaf(xv.w, wv.w, acc);
    }
    int d = min(g_degi[node], MAXDEG);
    float dv = rsqrtf(1.0f + (float)g_degi[node]);
    if (j == 0) g_dinv[node] = dv;
    // pad segment to multiple of 4 with dummy node NN (zero feature row)
    int p = (4 - (d & 3)) & 3;
    if (j < p) g_nbr2[node * MAXDEG + d + j] = NN;
    g_feat[blockIdx.x * 256 + threadIdx.x] = acc * dv;
}

// #4: pull layer 1 + fused layer-2. Warp per node; 8 lanes per row (float2 each),
// 4 neighbors per iteration; packed f32x2 accumulate; no inner predicates.
__global__ void k_pull1(const float* __restrict__ W2, const float* __restrict__ b1) {
    __shared__ float2 sW2[HID * 8];   // sW2[k*8+jj] = (W2[k][2jj], W2[k][2jj+1])
    __shared__ float2 sb2[8];
    for (int L = threadIdx.x; L < HID * 8; L += blockDim.x) {
        int k = L >> 3, jj = L & 7;
        sW2[L] = make_float2(W2[k * HID + 2*jj], W2[k * HID + 2*jj + 1]);
    }
    if (threadIdx.x < 8)
        sb2[threadIdx.x] = make_float2(b1[2*threadIdx.x], b1[2*threadIdx.x + 1]);
    __syncthreads();

    int warp = (blockIdx.x * blockDim.x + threadIdx.x) >> 5;
    if (warp >= NN) return;
    int lane = threadIdx.x & 31;
    int jj   = lane & 7;
    int qt   = lane >> 3;
    int start = warp * MAXDEG;
    int deg   = min(g_degi[warp], MAXDEG);
    int degp  = (deg + 3) & ~3;            // padded slots hold NN -> zero row
    unsigned long long acc = 0ull;         // packed (+0.0f, +0.0f)
    for (int base = 0; base < degp; base += 32) {
        int idx = base + lane;
        int myn = (idx < degp) ? g_nbr2[start + idx] : NN;
        int lim = min(32, degp - base);    // multiple of 4, warp-uniform
        for (int k = 0; k < lim; k += 4) {
            int r = __shfl_sync(0xffffffffu, myn, k + qt);
            unsigned long long v = *(const unsigned long long*)(g_feat + r * HID + 2*jj);
            padd_f32x2(acc, v);
        }
    }
    float2 a2;
    asm("mov.b64 {%0, %1}, %2;" : "=f"(a2.x), "=f"(a2.y) : "l"(acc));
    a2.x += __shfl_xor_sync(0xffffffffu, a2.x, 8);
    a2.y += __shfl_xor_sync(0xffffffffu, a2.y, 8);
    a2.x += __shfl_xor_sync(0xffffffffu, a2.x, 16);
    a2.y += __shfl_xor_sync(0xffffffffu, a2.y, 16);
    // ---- fused layer-2 transform (self term = own feat row) ----
    float dv = g_dinv[warp];
    float2 ag = *(const float2*)(g_feat + (size_t)warp * HID + 2*jj);
    float2 bb = sb2[jj];
    float2 hv;
    hv.x = fmaxf(fmaf(dv, ag.x + a2.x, bb.x), 0.f);
    hv.y = fmaxf(fmaf(dv, ag.y + a2.y, bb.y), 0.f);
    float2 ov = make_float2(0.f, 0.f);
    #pragma unroll
    for (int kk = 0; kk < 8; kk++) {
        float hx = __shfl_sync(0xffffffffu, hv.x, kk);
        float hy = __shfl_sync(0xffffffffu, hv.y, kk);
        float2 w0 = sW2[(2*kk    ) * 8 + jj];
        float2 w1 = sW2[(2*kk + 1) * 8 + jj];
        ov.x = fmaf(hx, w0.x, fmaf(hy, w1.x, ov.x));
        ov.y = fmaf(hx, w0.y, fmaf(hy, w1.y, ov.y));
    }
    ov.x *= dv; ov.y *= dv;
    if (lane < 8)
        *(float2*)(g_feat2 + (size_t)warp * HID + 2*jj) = ov;
}

// #5: pull layer 2 + fused h2 (fp16 out). Same structure over g_feat2.
__global__ void k_pull2(const float* __restrict__ b2) {
    __shared__ float2 sb2[8];
    if (threadIdx.x < 8)
        sb2[threadIdx.x] = make_float2(b2[2*threadIdx.x], b2[2*threadIdx.x + 1]);
    __syncthreads();
    int warp = (blockIdx.x * blockDim.x + threadIdx.x) >> 5;
    if (warp >= NN) return;
    int lane = threadIdx.x & 31;
    int jj   = lane & 7;
    int qt   = lane >> 3;
    int start = warp * MAXDEG;
    int deg   = min(g_degi[warp], MAXDEG);
    int degp  = (deg + 3) & ~3;
    unsigned long long acc = 0ull;
    for (int base = 0; base < degp; base += 32) {
        int idx = base + lane;
        int myn = (idx < degp) ? g_nbr2[start + idx] : NN;
        int lim = min(32, degp - base);
        for (int k = 0; k < lim; k += 4) {
            int r = __shfl_sync(0xffffffffu, myn, k + qt);
            unsigned long long v = *(const unsigned long long*)(g_feat2 + r * HID + 2*jj);
            padd_f32x2(acc, v);
        }
    }
    float2 a2;
    asm("mov.b64 {%0, %1}, %2;" : "=f"(a2.x), "=f"(a2.y) : "l"(acc));
    a2.x += __shfl_xor_sync(0xffffffffu, a2.x, 8);
    a2.y += __shfl_xor_sync(0xffffffffu, a2.y, 8);
    a2.x += __shfl_xor_sync(0xffffffffu, a2.x, 16);
    a2.y += __shfl_xor_sync(0xffffffffu, a2.y, 16);
    if (lane < 8) {
        float dv = g_dinv[warp];
        float2 ag = *(const float2*)(g_feat2 + (size_t)warp * HID + 2*jj);
        float2 bb = sb2[jj];
        float hx = fmaf(dv, ag.x + a2.x, bb.x);
        float hy = fmaf(dv, ag.y + a2.y, bb.y);
        ((half2*)g_h2)[(size_t)warp * 8 + jj] = __floats2half2_rn(hx, hy);
    }
}

// #6: score, 2 lanes per edge; fp16 rows = 1 sector per row.
__global__ void k_score(const void* __restrict__ ei, float* __restrict__ out) {
    int t = blockIdx.x * blockDim.x + threadIdx.x;
    long long e = t >> 1;
    if (e >= NE) return;
    int p = t & 1;
    int is64 = g_is64;
    int r = load_idx1(ei, e, is64);
    int c = load_idx1(ei, (long long)NE + e, is64);
    uint4 av = __ldg(&g_h2[(size_t)r * 2 + p]);
    uint4 bv = __ldg(&g_h2[(size_t)c * 2 + p]);
    const half2* ah = (const half2*)&av;
    const half2* bh = (const half2*)&bv;
    float s = 0.f;
    #pragma unroll
    for (int q = 0; q < 4; q++) {
        float2 a = __half22float2(ah[q]);
        float2 b = __half22float2(bh[q]);
        s = fmaf(a.x, b.x, fmaf(a.y, b.y, s));
    }
    s += __shfl_xor_sync(0xffffffffu, s, 1);
    if (p == 0) out[e] = 1.0f / (1.0f + __expf(-s));
}

extern "C" void kernel_launch(void* const* d_in, const int* in_sizes, int n_in,
                              void* d_out, int out_size) {
    const float* x  = nullptr;
    const void*  ei = nullptr;
    const float* W1 = nullptr;
    const float* b1 = nullptr;
    const float* W2 = nullptr;
    const float* b2 = nullptr;
    for (int i = 0; i < n_in; i++) {
        long long n = in_sizes[i];
        if      (n == (long long)NN * CIN)      x  = (const float*)d_in[i];
        else if (n == 2LL * NE)                 ei = d_in[i];
        else if (n == CIN * HID)                W1 = (const float*)d_in[i];
        else if (n == HID * HID)                W2 = (const float*)d_in[i];
        else if (n == HID) { if (!b1) b1 = (const float*)d_in[i]; else b2 = (const float*)d_in[i]; }
    }
    float* out = (float*)d_out;

    const int TB  = 256;
    const int gn  = (NN + TB - 1) / TB;
    const int ge4 = (NE / 4 + TB - 1) / TB;
    const int gw  = (NN * 32 + TB - 1) / TB;            // warp per node
    const int gs  = ((long long)NE * 2 + TB - 1) / TB;  // 2 lanes per edge

    k_init     <<<gn,  TB>>>(ei);           // #1
    k_deg_store<<<ge4, TB>>>(ei);           // #2
    k_xform1   <<<NN/16, TB>>>(x, W1);      // #3 (+ dinv + pad)
    k_pull1    <<<gw,  TB>>>(W2, b1);       // #4  <- profiler slot
    k_pull2    <<<gw,  TB>>>(b2);           // #5
    k_score    <<<gs,  TB>>>(ei, out);      // #6
}